// round 7
// baseline (speedup 1.0000x reference)
#include <cuda_runtime.h>
#include <math.h>
#include <stdint.h>

#define Nn 4096
#define HIDD 512
#define TT 9332
#define CUNIT 896.0f
#define SCALE 0.08838834764831843f

__device__ float g_bias[(size_t)Nn * Nn];
__device__ int   g_idx[Nn];
__device__ float g_rowmin[Nn];
__device__ float g_bhmin;
__device__ float g_h[(size_t)Nn * HIDD];
__device__ float g_xn[(size_t)Nn * HIDD];
__device__ float g_qkv[(size_t)Nn * 3 * HIDD];
__device__ float g_ao[(size_t)Nn * HIDD];
__device__ float g_mid[(size_t)Nn * 4 * HIDD];
__device__ float g_part[32 * HIDD];

__device__ __forceinline__ unsigned long long pk2(float lo, float hi) {
    unsigned long long r; asm("mov.b64 %0, {%1, %2};" : "=l"(r) : "f"(lo), "f"(hi)); return r;
}
__device__ __forceinline__ float2 upk2(unsigned long long v) {
    float2 r; asm("mov.b64 {%0, %1}, %2;" : "=f"(r.x), "=f"(r.y) : "l"(v)); return r;
}
__device__ __forceinline__ void fma2(unsigned long long &d, unsigned long long a, unsigned long long b) {
    asm("fma.rn.f32x2 %0, %1, %2, %0;" : "+l"(d) : "l"(a), "l"(b));
}

__global__ void k_coord(const float* __restrict__ x) {
    __shared__ float sx[1024], sy[1024];
    int t = threadIdx.x;
    float mx = INFINITY, my = INFINITY;
    for (int n = t; n < Nn; n += 1024) {
        mx = fminf(mx, x[(size_t)n * 1026 + 1024]);
        my = fminf(my, x[(size_t)n * 1026 + 1025]);
    }
    sx[t] = mx; sy[t] = my; __syncthreads();
    for (int s = 512; s > 0; s >>= 1) {
        if (t < s) { sx[t] = fminf(sx[t], sx[t+s]); sy[t] = fminf(sy[t], sy[t+s]); }
        __syncthreads();
    }
    float minx = sx[0], miny = sy[0];
    for (int n = t; n < Nn; n += 1024) {
        float xp = rintf((x[(size_t)n * 1026 + 1024] - minx) / CUNIT);
        float yp = rintf((x[(size_t)n * 1026 + 1025] - miny) / CUNIT);
        g_idx[n] = (int)(xp * 300.0f + yp);
    }
}

__global__ __launch_bounds__(256) void k_gather(const float* __restrict__ tab) {
    __shared__ int sidx[Nn];
    __shared__ float red[256];
    int t = threadIdx.x, b = blockIdx.x;
    for (int i = t; i < Nn; i += 256) sidx[i] = g_idx[i];
    __syncthreads();
    const float* row = tab + (size_t)sidx[b] * TT;
    float* outr = g_bias + (size_t)b * Nn;
    float lm = INFINITY;
    for (int m = t; m < Nn; m += 256) {
        float v = row[sidx[m]];
        outr[m] = v;
        lm = fminf(lm, v);
    }
    red[t] = lm; __syncthreads();
    for (int s = 128; s > 0; s >>= 1) { if (t < s) red[t] = fminf(red[t], red[t+s]); __syncthreads(); }
    if (t == 0) g_rowmin[b] = red[0];
}

__global__ void k_minb() {
    __shared__ float red[1024];
    int t = threadIdx.x;
    float m = INFINITY;
    for (int i = t; i < Nn; i += 1024) m = fminf(m, g_rowmin[i]);
    red[t] = m; __syncthreads();
    for (int s = 512; s > 0; s >>= 1) { if (t < s) red[t] = fminf(red[t], red[t+s]); __syncthreads(); }
    if (t == 0) g_bhmin = 0.25f * red[0];
}

// C = act(A*B (+bias)) (+=C). ACT:0 none,1 relu,2 gelu-exact
template<int ACT, int RESID, int HASB>
__global__ __launch_bounds__(256) void gemm_k(const float* __restrict__ A, const float* __restrict__ B,
                                              const float* __restrict__ bias, float* __restrict__ C,
                                              int K, int lda, int ldb, int ldc) {
    __shared__ __align__(16) float As[8 * 132];
    __shared__ __align__(16) float Bs[8 * 132];
    const int tid = threadIdx.x;
    const int tx = tid & 15, ty = tid >> 4;
    const int m0 = blockIdx.y * 128, n0 = blockIdx.x * 128;
    unsigned long long acc[8][4];
#pragma unroll
    for (int i = 0; i < 8; i++)
#pragma unroll
        for (int j = 0; j < 4; j++) acc[i][j] = 0ull;

    for (int k0 = 0; k0 < K; k0 += 8) {
#pragma unroll
        for (int i = 0; i < 4; i++) {
            int idx = tid + i * 256;
            int mm = idx >> 3, kk = idx & 7;
            As[kk * 132 + mm] = A[(size_t)(m0 + mm) * lda + k0 + kk];
            int kk2 = idx >> 7, nn = idx & 127;
            Bs[kk2 * 132 + nn] = B[(size_t)(k0 + kk2) * ldb + n0 + nn];
        }
        __syncthreads();
#pragma unroll
        for (int kk = 0; kk < 8; kk++) {
            const float4 a0 = *(const float4*)&As[kk * 132 + ty * 8];
            const float4 a1 = *(const float4*)&As[kk * 132 + ty * 8 + 4];
            const unsigned long long* bp = (const unsigned long long*)&Bs[kk * 132 + tx * 8];
            unsigned long long b0 = bp[0], b1 = bp[1], b2 = bp[2], b3 = bp[3];
            unsigned long long av[8];
            av[0]=pk2(a0.x,a0.x); av[1]=pk2(a0.y,a0.y); av[2]=pk2(a0.z,a0.z); av[3]=pk2(a0.w,a0.w);
            av[4]=pk2(a1.x,a1.x); av[5]=pk2(a1.y,a1.y); av[6]=pk2(a1.z,a1.z); av[7]=pk2(a1.w,a1.w);
#pragma unroll
            for (int i = 0; i < 8; i++) {
                fma2(acc[i][0], av[i], b0); fma2(acc[i][1], av[i], b1);
                fma2(acc[i][2], av[i], b2); fma2(acc[i][3], av[i], b3);
            }
        }
        __syncthreads();
    }
#pragma unroll
    for (int i = 0; i < 8; i++) {
        float* crow = C + (size_t)(m0 + ty * 8 + i) * ldc + n0 + tx * 8;
#pragma unroll
        for (int j = 0; j < 4; j++) {
            float2 v = upk2(acc[i][j]);
            int col = n0 + tx * 8 + j * 2;
            float x0 = v.x, x1 = v.y;
            if (HASB) { x0 += bias[col]; x1 += bias[col + 1]; }
            if (ACT == 1) { x0 = fmaxf(x0, 0.f); x1 = fmaxf(x1, 0.f); }
            if (ACT == 2) {
                x0 = 0.5f * x0 * (1.f + erff(x0 * 0.7071067811865475f));
                x1 = 0.5f * x1 * (1.f + erff(x1 * 0.7071067811865475f));
            }
            if (RESID) { x0 += crow[j * 2]; x1 += crow[j * 2 + 1]; }
            crow[j * 2] = x0; crow[j * 2 + 1] = x1;
        }
    }
}

__global__ __launch_bounds__(256) void ln_k(const float* __restrict__ in, float* __restrict__ out,
                                            const float* __restrict__ sc, const float* __restrict__ bi) {
    __shared__ float red[256];
    int n = blockIdx.x, t = threadIdx.x;
    const float* row = in + (size_t)n * HIDD;
    float v0 = row[t], v1 = row[t + 256];
    red[t] = v0 + v1; __syncthreads();
    for (int s = 128; s > 0; s >>= 1) { if (t < s) red[t] += red[t+s]; __syncthreads(); }
    float mean = red[0] * (1.f / 512.f); __syncthreads();
    float d0 = v0 - mean, d1 = v1 - mean;
    red[t] = d0 * d0 + d1 * d1; __syncthreads();
    for (int s = 128; s > 0; s >>= 1) { if (t < s) red[t] += red[t+s]; __syncthreads(); }
    float inv = rsqrtf(0.f) == rsqrtf(0.f) ? 1.f / sqrtf(red[0] * (1.f / 512.f) + 1e-5f)
                                           : 0.f;  // keep IEEE path
    float* orow = out + (size_t)n * HIDD;
    orow[t]       = d0 * inv * sc[t] + bi[t];
    orow[t + 256] = d1 * inv * sc[t + 256] + bi[t + 256];
}

#define ATTN_SMEM ((8192 + 8320 + 8192 + 4096) * 4)
__global__ __launch_bounds__(256) void attn_k(const float* __restrict__ qkv,
                                              const float* __restrict__ bias, int local) {
    extern __shared__ float sm[];
    float* Qs = sm;
    float* Kst = sm + 8192;
    float* Vs = sm + 8192 + 8320;
    float* Ps = sm + 8192 + 8320 + 8192;
    const int tid = threadIdx.x, w = tid >> 5, lane = tid & 31;
    const int head = blockIdx.y, q0 = blockIdx.x * 64;
    const float slope = 1.0f / (float)(4 << (2 * head));
    const float bh = g_bhmin;

    for (int i = tid; i < 64 * 128; i += 256) {
        int r = i >> 7, d = i & 127;
        Qs[i] = qkv[(size_t)(q0 + r) * 1536 + head * 128 + d];
    }
    float o[8][4], mi[8], li[8];
#pragma unroll
    for (int qi = 0; qi < 8; qi++) {
        mi[qi] = -INFINITY; li[qi] = 0.f;
        o[qi][0] = o[qi][1] = o[qi][2] = o[qi][3] = 0.f;
    }

    for (int t0 = 0; t0 < Nn; t0 += 64) {
        __syncthreads();
        for (int i = tid; i < 64 * 128; i += 256) {
            int r = i >> 7, d = i & 127;
            const float* kv = qkv + (size_t)(t0 + r) * 1536 + head * 128;
            Kst[d * 65 + r] = kv[512 + d];
            Vs[i] = kv[1024 + d];
        }
        __syncthreads();

        float s0[8], s1[8];
#pragma unroll
        for (int qi = 0; qi < 8; qi++) { s0[qi] = 0.f; s1[qi] = 0.f; }
        const float* qbase = Qs + (w * 8) * 128;
        for (int d = 0; d < 128; d++) {
            float k0 = Kst[d * 65 + lane];
            float k1 = Kst[d * 65 + 32 + lane];
#pragma unroll
            for (int qi = 0; qi < 8; qi++) {
                float q = qbase[qi * 128 + d];
                s0[qi] += q * k0; s1[qi] += q * k1;
            }
        }
#pragma unroll
        for (int qi = 0; qi < 8; qi++) {
            const float* brow = bias + (size_t)(q0 + w * 8 + qi) * Nn + t0;
            float b0 = slope * brow[lane];
            float b1 = slope * brow[32 + lane];
            if (local) { if (b0 == bh) b0 = -INFINITY; if (b1 == bh) b1 = -INFINITY; }
            float v0 = s0[qi] * SCALE + b0;
            float v1 = s1[qi] * SCALE + b1;
            float rm = fmaxf(v0, v1);
#pragma unroll
            for (int off = 16; off > 0; off >>= 1) rm = fmaxf(rm, __shfl_xor_sync(0xffffffffu, rm, off));
            float nm = fmaxf(mi[qi], rm);
            float alpha, p0, p1;
            if (nm == -INFINITY) { alpha = 1.f; p0 = 0.f; p1 = 0.f; }
            else { alpha = expf(mi[qi] - nm); p0 = expf(v0 - nm); p1 = expf(v1 - nm); }
            float ps = p0 + p1;
#pragma unroll
            for (int off = 16; off > 0; off >>= 1) ps += __shfl_xor_sync(0xffffffffu, ps, off);
            li[qi] = li[qi] * alpha + ps;
            mi[qi] = nm;
            o[qi][0] *= alpha; o[qi][1] *= alpha; o[qi][2] *= alpha; o[qi][3] *= alpha;
            Ps[(w * 8 + qi) * 64 + lane] = p0;
            Ps[(w * 8 + qi) * 64 + 32 + lane] = p1;
        }
        __syncwarp();
        for (int kj = 0; kj < 64; kj++) {
            float v0 = Vs[kj * 128 + lane];
            float v1 = Vs[kj * 128 + 32 + lane];
            float v2 = Vs[kj * 128 + 64 + lane];
            float v3 = Vs[kj * 128 + 96 + lane];
#pragma unroll
            for (int qi = 0; qi < 8; qi++) {
                float p = Ps[(w * 8 + qi) * 64 + kj];
                o[qi][0] += p * v0; o[qi][1] += p * v1;
                o[qi][2] += p * v2; o[qi][3] += p * v3;
            }
        }
    }
#pragma unroll
    for (int qi = 0; qi < 8; qi++) {
        float inv = 1.0f / li[qi];
        float* op = g_ao + (size_t)(q0 + w * 8 + qi) * HIDD + head * 128;
        op[lane] = o[qi][0] * inv;
        op[32 + lane] = o[qi][1] * inv;
        op[64 + lane] = o[qi][2] * inv;
        op[96 + lane] = o[qi][3] * inv;
    }
}

__global__ __launch_bounds__(512) void colsum_k(const float* __restrict__ h) {
    int c = threadIdx.x, b = blockIdx.x;
    float s = 0.f;
    for (int n = b * 128; n < (b + 1) * 128; n++) s += h[(size_t)n * HIDD + c];
    g_part[b * HIDD + c] = s;
}

__global__ __launch_bounds__(512) void final_k(const float* __restrict__ ns, const float* __restrict__ nb,
                                               const float* __restrict__ hw, const float* __restrict__ hb,
                                               float* __restrict__ out) {
    __shared__ float red[512], red2[512];
    int c = threadIdx.x;
    float s = 0.f;
    for (int b = 0; b < 32; b++) s += g_part[b * HIDD + c];
    float mc = s * (1.f / 4096.f);
    red[c] = mc; __syncthreads();
    for (int st = 256; st > 0; st >>= 1) { if (c < st) red[c] += red[c+st]; __syncthreads(); }
    float mean = red[0] * (1.f / 512.f); __syncthreads();
    float d = mc - mean;
    red[c] = d * d; __syncthreads();
    for (int st = 256; st > 0; st >>= 1) { if (c < st) red[c] += red[c+st]; __syncthreads(); }
    float inv = 1.f / sqrtf(red[0] * (1.f / 512.f) + 1e-5f);
    float hm = d * inv * ns[c] + nb[c];
    __syncthreads();
    red[c] = hm * hw[c * 2]; red2[c] = hm * hw[c * 2 + 1];
    __syncthreads();
    for (int st = 256; st > 0; st >>= 1) {
        if (c < st) { red[c] += red[c+st]; red2[c] += red2[c+st]; }
        __syncthreads();
    }
    if (c == 0) { out[0] = red[0] + hb[0]; out[1] = red2[0] + hb[1]; }
}

extern "C" void kernel_launch(void* const* d_in, const int* in_sizes, int n_in,
                              void* d_out, int out_size) {
    const float* x      = (const float*)d_in[0];
    const float* tab    = (const float*)d_in[1];
    const float* fc1_w  = (const float*)d_in[2];
    const float* fc1_b  = (const float*)d_in[3];
    const float* ln1_s  = (const float*)d_in[4];
    const float* ln1_b  = (const float*)d_in[5];
    const float* qkv_w  = (const float*)d_in[6];
    const float* proj_w = (const float*)d_in[7];
    const float* proj_b = (const float*)d_in[8];
    const float* ln2_s  = (const float*)d_in[9];
    const float* ln2_b  = (const float*)d_in[10];
    const float* mlp1_w = (const float*)d_in[11];
    const float* mlp1_b = (const float*)d_in[12];
    const float* mlp2_w = (const float*)d_in[13];
    const float* mlp2_b = (const float*)d_in[14];
    const float* norm_s = (const float*)d_in[15];
    const float* norm_b = (const float*)d_in[16];
    const float* head_w = (const float*)d_in[17];
    const float* head_b = (const float*)d_in[18];
    float* out = (float*)d_out;

    float *p_h, *p_xn, *p_qkv, *p_ao, *p_mid, *p_bias;
    cudaGetSymbolAddress((void**)&p_h, g_h);
    cudaGetSymbolAddress((void**)&p_xn, g_xn);
    cudaGetSymbolAddress((void**)&p_qkv, g_qkv);
    cudaGetSymbolAddress((void**)&p_ao, g_ao);
    cudaGetSymbolAddress((void**)&p_mid, g_mid);
    cudaGetSymbolAddress((void**)&p_bias, g_bias);
    cudaFuncSetAttribute(attn_k, cudaFuncAttributeMaxDynamicSharedMemorySize, ATTN_SMEM);

    k_coord<<<1, 1024>>>(x);
    k_gather<<<Nn, 256>>>(tab);
    k_minb<<<1, 1024>>>();

    gemm_k<1,0,1><<<dim3(4, 32), 256>>>(x, fc1_w, fc1_b, p_h, 1024, 1026, 512, 512);

    for (int l = 0; l < 3; l++) {
        ln_k<<<Nn, 256>>>(p_h, p_xn, ln1_s + l * 512, ln1_b + l * 512);
        gemm_k<0,0,0><<<dim3(12, 32), 256>>>(p_xn, qkv_w + (size_t)l * 512 * 1536,
                                             (const float*)0, p_qkv, 512, 512, 1536, 1536);
        attn_k<<<dim3(64, 4), 256, ATTN_SMEM>>>(p_qkv, p_bias, (l < 2) ? 1 : 0);
        gemm_k<0,1,1><<<dim3(4, 32), 256>>>(p_ao, proj_w + (size_t)l * 512 * 512,
                                            proj_b + l * 512, p_h, 512, 512, 512, 512);
        ln_k<<<Nn, 256>>>(p_h, p_xn, ln2_s + l * 512, ln2_b + l * 512);
        gemm_k<2,0,1><<<dim3(16, 32), 256>>>(p_xn, mlp1_w + (size_t)l * 512 * 2048,
                                             mlp1_b + (size_t)l * 2048, p_mid, 512, 512, 2048, 2048);
        gemm_k<0,1,1><<<dim3(4, 32), 256>>>(p_mid, mlp2_w + (size_t)l * 2048 * 512,
                                            mlp2_b + l * 512, p_h, 2048, 2048, 512, 512);
    }
    colsum_k<<<32, 512>>>(p_h);
    final_k<<<1, 512>>>(norm_s, norm_b, head_w, head_b, out);
}